// round 1
// baseline (speedup 1.0000x reference)
#include <cuda_runtime.h>
#include <cuda_bf16.h>
#include <cstddef>

#define N_NODES 100000
#define N_EDGES 1200000
#define HID 64
#define F_IN 16
#define G_GRAPHS 1024

// ---------------- scratch (device globals; no allocation) ----------------
__device__ float g_aggr[(size_t)N_NODES * HID];
__device__ float g_h1 [(size_t)N_NODES * HID];
__device__ float g_h2 [(size_t)N_NODES * HID];
__device__ float g_bufA[(size_t)N_NODES * HID];
__device__ float g_bufB[(size_t)N_NODES * HID];
__device__ float g_stats[2 * HID];            // [0:64) sum, [64:128) sumsq
__device__ float g_pool[(size_t)G_GRAPHS * HID];
__device__ float g_cnt [G_GRAPHS];

// ---------------- zeroing ----------------
__global__ void zero_layer_kernel(int aggr_count) {
    int i = blockIdx.x * blockDim.x + threadIdx.x;
    if (i < aggr_count) g_aggr[i] = 0.0f;
    if (i < 2 * HID)    g_stats[i] = 0.0f;
}

__global__ void zero_pool_kernel() {
    int i = blockIdx.x * blockDim.x + threadIdx.x;
    if (i < G_GRAPHS * HID) g_pool[i] = 0.0f;
    if (i < G_GRAPHS)       g_cnt[i]  = 0.0f;
}

// ---------------- edge scatter-add (float4 atomics, sm_90+) ----------------
template <int D>
__global__ void scatter_kernel(const float* __restrict__ x,
                               const int* __restrict__ src,
                               const int* __restrict__ dst) {
    constexpr int C = D / 4;                  // float4 chunks per edge
    int idx = blockIdx.x * blockDim.x + threadIdx.x;
    if (idx >= N_EDGES * C) return;
    int e = idx / C;
    int q = idx - e * C;
    int s = src[e];
    int d = dst[e];
    float4 v = reinterpret_cast<const float4*>(x + (size_t)s * D)[q];
#if __CUDA_ARCH__ >= 900
    atomicAdd(reinterpret_cast<float4*>(g_aggr + (size_t)d * D) + q, v);
#else
    float* a = g_aggr + (size_t)d * D + q * 4;
    atomicAdd(a + 0, v.x); atomicAdd(a + 1, v.y);
    atomicAdd(a + 2, v.z); atomicAdd(a + 3, v.w);
#endif
}

// ---------------- tiled GEMM [N,K] @ [K,64] + bias, ReLU ----------------
// AGGR_IN: input = (1+eps)*X + g_aggr (GIN combine fused into the load)
// STATS  : accumulate per-column sum/sumsq of the ReLU'd output into g_stats
template <int K, bool AGGR_IN, bool STATS>
__global__ void gemm_kernel(const float* __restrict__ X,
                            const float* __restrict__ W,
                            const float* __restrict__ bias,
                            const float* __restrict__ eps_p,
                            float* __restrict__ out) {
    __shared__ float sW[K * 64];
    __shared__ float sIn[32 * K];
    __shared__ float sSum[64];
    __shared__ float sSq[64];

    const int tid = threadIdx.x;              // 256 threads
    const int col = tid & 63;
    const int ty  = tid >> 6;                 // 0..3
    const size_t row0 = (size_t)blockIdx.x * 32;

    // load weights
    for (int i = tid; i < K * 64; i += 256) sW[i] = W[i];

    // load 32 input rows (fused GIN combine)
    float epsv = 1.0f;
    if (AGGR_IN) epsv = 1.0f + *eps_p;
    for (int i = tid; i < 32 * K; i += 256) {
        size_t gi = row0 * K + i;             // contiguous => coalesced
        float v = X[gi];
        if (AGGR_IN) v = epsv * v + g_aggr[gi];
        sIn[i] = v;
    }
    if (STATS && ty == 0) { sSum[col] = 0.0f; sSq[col] = 0.0f; }
    __syncthreads();

    float acc[8];
    const float b = bias[col];
#pragma unroll
    for (int j = 0; j < 8; j++) acc[j] = b;

#pragma unroll
    for (int k = 0; k < K; k++) {
        float w = sW[k * 64 + col];
#pragma unroll
        for (int j = 0; j < 8; j++)
            acc[j] += sIn[(ty + 4 * j) * K + k] * w;
    }

    float ls = 0.0f, lss = 0.0f;
#pragma unroll
    for (int j = 0; j < 8; j++) {
        float v = fmaxf(acc[j], 0.0f);
        out[(row0 + ty + 4 * j) * 64 + col] = v;
        if (STATS) { ls += v; lss += v * v; }
    }

    if (STATS) {
        atomicAdd(&sSum[col], ls);
        atomicAdd(&sSq[col],  lss);
        __syncthreads();
        if (ty == 0) {
            atomicAdd(&g_stats[col],      sSum[col]);
            atomicAdd(&g_stats[64 + col], sSq[col]);
        }
    }
}

// ---------------- BatchNorm apply (training-mode batch stats) ----------------
__global__ void bn_apply_kernel(const float* __restrict__ h,
                                const float* __restrict__ gamma,
                                const float* __restrict__ beta,
                                float* __restrict__ out) {
    int i = blockIdx.x * blockDim.x + threadIdx.x;
    if (i >= N_NODES * HID) return;
    int f = i & 63;
    const float invN = 1.0f / (float)N_NODES;
    float mean = g_stats[f] * invN;
    float var  = g_stats[64 + f] * invN - mean * mean;
    float sc   = gamma[f] * rsqrtf(var + 1e-5f);
    out[i] = (h[i] - mean) * sc + beta[f];
}

// ---------------- global mean pool (float4 atomics) ----------------
__global__ void pool_kernel(const float* __restrict__ h,
                            const int* __restrict__ batch) {
    int i = blockIdx.x * blockDim.x + threadIdx.x;   // over N*16 float4 chunks
    if (i >= N_NODES * 16) return;
    int n = i >> 4;
    int q = i & 15;
    int g = batch[n];
    float4 v = reinterpret_cast<const float4*>(h)[i];
#if __CUDA_ARCH__ >= 900
    atomicAdd(reinterpret_cast<float4*>(g_pool) + (size_t)g * 16 + q, v);
#else
    float* p = g_pool + (size_t)g * 64 + q * 4;
    atomicAdd(p + 0, v.x); atomicAdd(p + 1, v.y);
    atomicAdd(p + 2, v.z); atomicAdd(p + 3, v.w);
#endif
    if (q == 0) atomicAdd(&g_cnt[g], 1.0f);
}

// ---------------- readout MLP: [G,64]@[64,10] relu @[10,1] ----------------
__global__ void readout_kernel(const float* __restrict__ Wf1,
                               const float* __restrict__ bf1,
                               const float* __restrict__ Wf2,
                               const float* __restrict__ bf2,
                               float* __restrict__ out) {
    int g = blockIdx.x * blockDim.x + threadIdx.x;
    if (g >= G_GRAPHS) return;
    float inv = 1.0f / fmaxf(g_cnt[g], 1.0f);
    float hid[10];
#pragma unroll
    for (int j = 0; j < 10; j++) hid[j] = bf1[j];
    for (int k = 0; k < 64; k++) {
        float p = g_pool[(size_t)g * 64 + k] * inv;
#pragma unroll
        for (int j = 0; j < 10; j++) hid[j] += p * Wf1[k * 10 + j];
    }
    float o = bf2[0];
#pragma unroll
    for (int j = 0; j < 10; j++) o += fmaxf(hid[j], 0.0f) * Wf2[j];
    out[g] = o;
}

// ---------------- host launcher ----------------
static inline int cdiv(long long a, int b) { return (int)((a + b - 1) / b); }

extern "C" void kernel_launch(void* const* d_in, const int* in_sizes, int n_in,
                              void* d_out, int out_size) {
    (void)in_sizes; (void)n_in;
    const float* x    = (const float*)d_in[0];
    const int*   ei   = (const int*)  d_in[1];
    const int*   batch= (const int*)  d_in[2];
    const float* W1a = (const float*)d_in[3];  const float* b1a = (const float*)d_in[4];
    const float* W1b = (const float*)d_in[5];  const float* b1b = (const float*)d_in[6];
    const float* e1  = (const float*)d_in[7];
    const float* g1  = (const float*)d_in[8];  const float* be1 = (const float*)d_in[9];
    const float* W2a = (const float*)d_in[10]; const float* b2a = (const float*)d_in[11];
    const float* W2b = (const float*)d_in[12]; const float* b2b = (const float*)d_in[13];
    const float* e2  = (const float*)d_in[14];
    const float* g2  = (const float*)d_in[15]; const float* be2 = (const float*)d_in[16];
    const float* W3a = (const float*)d_in[17]; const float* b3a = (const float*)d_in[18];
    const float* W3b = (const float*)d_in[19]; const float* b3b = (const float*)d_in[20];
    const float* e3  = (const float*)d_in[21];
    const float* g3  = (const float*)d_in[22]; const float* be3 = (const float*)d_in[23];
    const float* Wf1 = (const float*)d_in[24]; const float* bf1 = (const float*)d_in[25];
    const float* Wf2 = (const float*)d_in[26]; const float* bf2 = (const float*)d_in[27];
    float* out = (float*)d_out; (void)out_size;

    const int* src = ei;             // edge_index[0]
    const int* dst = ei + N_EDGES;   // edge_index[1]

    // device-global scratch pointers (host-visible addresses)
    void *p_h1, *p_h2, *p_bufA, *p_bufB;
    cudaGetSymbolAddress(&p_h1,  g_h1);
    cudaGetSymbolAddress(&p_h2,  g_h2);
    cudaGetSymbolAddress(&p_bufA, g_bufA);
    cudaGetSymbolAddress(&p_bufB, g_bufB);
    float* h1  = (float*)p_h1;
    float* h2  = (float*)p_h2;
    float* bfA = (float*)p_bufA;
    float* bfB = (float*)p_bufB;

    const int TB = 256;
    const int gemm_blocks = N_NODES / 32;          // 3125 (exact)
    const int nh = N_NODES * HID;                  // 6.4M

    // ===== layer 1 (input F_IN=16) =====
    zero_layer_kernel<<<cdiv(N_NODES * F_IN, TB), TB>>>(N_NODES * F_IN);
    scatter_kernel<F_IN><<<cdiv((long long)N_EDGES * (F_IN/4), TB), TB>>>(x, src, dst);
    gemm_kernel<F_IN, true,  false><<<gemm_blocks, TB>>>(x,  W1a, b1a, e1, h1);
    gemm_kernel<HID,  false, true ><<<gemm_blocks, TB>>>(h1, W1b, b1b, nullptr, h2);
    bn_apply_kernel<<<cdiv(nh, TB), TB>>>(h2, g1, be1, bfA);

    // ===== layer 2 =====
    zero_layer_kernel<<<cdiv(nh, TB), TB>>>(nh);
    scatter_kernel<HID><<<cdiv((long long)N_EDGES * (HID/4), TB), TB>>>(bfA, src, dst);
    gemm_kernel<HID, true,  false><<<gemm_blocks, TB>>>(bfA, W2a, b2a, e2, h1);
    gemm_kernel<HID, false, true ><<<gemm_blocks, TB>>>(h1,  W2b, b2b, nullptr, h2);
    bn_apply_kernel<<<cdiv(nh, TB), TB>>>(h2, g2, be2, bfB);

    // ===== layer 3 =====
    zero_layer_kernel<<<cdiv(nh, TB), TB>>>(nh);
    scatter_kernel<HID><<<cdiv((long long)N_EDGES * (HID/4), TB), TB>>>(bfB, src, dst);
    gemm_kernel<HID, true,  false><<<gemm_blocks, TB>>>(bfB, W3a, b3a, e3, h1);
    gemm_kernel<HID, false, true ><<<gemm_blocks, TB>>>(h1,  W3b, b3b, nullptr, h2);
    bn_apply_kernel<<<cdiv(nh, TB), TB>>>(h2, g3, be3, bfA);

    // ===== pool + readout =====
    zero_pool_kernel<<<cdiv(G_GRAPHS * HID, TB), TB>>>();
    pool_kernel<<<cdiv(N_NODES * 16, TB), TB>>>(bfA, batch);
    readout_kernel<<<cdiv(G_GRAPHS, TB), TB>>>(Wf1, bf1, Wf2, bf2, out);
}